// round 1
// baseline (speedup 1.0000x reference)
#include <cuda_runtime.h>

// Problem constants
#define BB 16
#define DD 16
#define HH 128
#define WW 160
#define ROW4   (WW*4)        // 640 float4 per (b,h) row in (B,H,W,D) layout
#define TH     8             // rows per block in iteration kernel
#define NCHUNK (HH/TH)       // 16
#define PLANE4 (HH*WW*4)     // float4 per image
#define NV4    (BB*HH*WW*4)  // total float4 per field = 1,310,720

// Chebyshev on spectrum [1, 9] (Gershgorin: diag = 1+Sw, off-diag sum = Sw, Sw<=4)
#define THETA 5.0
#define DELTA 4.0
#define N_UPDATES 28
#define N_FULL (N_UPDATES-1)

// Scratch (static device arrays; no allocation allowed)
__device__ float4 g_bt[NV4];      // b in (B,H,W,D) layout
__device__ float4 g_x[2][NV4];    // x ping-pong
__device__ float4 g_d[2][NV4];    // d ping-pong

// -------------------- transpose (B,D,H,W) -> (B,H,W,D) --------------------
__global__ void transpose_in_kernel(const float* __restrict__ ae,
                                    float* __restrict__ bt)
{
    __shared__ float sm[32*17];
    int blk = blockIdx.x;
    int wt = blk % (WW/32); blk /= (WW/32);
    int h  = blk % HH;      blk /= HH;
    int b  = blk;
    int w0 = wt * 32;
    int t = threadIdx.x;              // 512 threads
    {
        int c = t >> 5, wl = t & 31;  // coalesced read along w per channel
        float v = ae[(((size_t)b*DD + c)*HH + h)*WW + w0 + wl];
        sm[wl*17 + c] = v;
    }
    __syncthreads();
    {
        int wl = t >> 4, c = t & 15;  // coalesced contiguous write
        bt[((((size_t)b*HH + h)*WW) + w0)*DD + t] = sm[wl*17 + c];
    }
}

// -------------------- fused Chebyshev iteration --------------------
// INIT=true : x := b (implicit), d_out = c2 * (b - A b)    (c1 unused = 0)
// INIT=false: s = x_in + d_in ; x_out = s ; d_out = c1*d_in + c2*(b - A s)
template<bool INIT>
__global__ void __launch_bounds__(ROW4)
cheb_iter(const float4* __restrict__ x_in,
          const float4* __restrict__ d_in,
          const float4* __restrict__ b_in,
          const float*  __restrict__ wxy,
          float4* __restrict__ x_out,
          float4* __restrict__ d_out,
          float c1, float c2)
{
    __shared__ float4 sring[4][ROW4];   // 40KB ring of s = x+d rows
    const int t  = threadIdx.x;         // 640
    const int w  = t >> 2;
    const int blk = blockIdx.x;
    const int bi  = blk / NCHUNK;
    const int h0  = (blk - bi*NCHUNK) * TH;
    const size_t base = (size_t)bi * PLANE4;
    const float* wx = wxy + ((size_t)bi*2    )*HH*WW;
    const float* wy = wxy + ((size_t)bi*2 + 1)*HH*WW;

    float4 d_pipe = make_float4(0.f,0.f,0.f,0.f);

    #pragma unroll 1
    for (int hh = h0-1; hh <= h0+TH; ++hh) {
        float4 d_ld = make_float4(0.f,0.f,0.f,0.f);
        float4 s    = make_float4(0.f,0.f,0.f,0.f);
        if (hh >= 0 && hh < HH) {
            size_t idx = base + (size_t)hh*ROW4 + t;
            float4 xv = x_in[idx];
            if (!INIT) {
                d_ld = d_in[idx];
                s.x = xv.x + d_ld.x; s.y = xv.y + d_ld.y;
                s.z = xv.z + d_ld.z; s.w = xv.w + d_ld.w;
            } else {
                s = xv;
            }
        }
        sring[hh & 3][t] = s;
        __syncthreads();

        const int hc = hh - 1;
        if (hc >= h0 && hc < h0 + TH) {
            const float4 z  = make_float4(0.f,0.f,0.f,0.f);
            float4 sc = sring[hc & 3][t];
            float4 sl = (w > 0)     ? sring[hc & 3][t-4] : z;
            float4 sr = (w < WW-1)  ? sring[hc & 3][t+4] : z;
            float4 su = sring[(hc-1) & 3][t];   // zeros were stored for hh = -1
            float4 sd = sring[(hc+1) & 3][t];   // zeros were stored for hh = HH

            int woff  = hc*WW + w;
            float wxm = (w > 0)     ? wx[woff-1]  : 0.f;
            float wxp = (w < WW-1)  ? wx[woff]    : 0.f;
            float wym = (hc > 0)    ? wy[woff-WW] : 0.f;
            float wyp = (hc < HH-1) ? wy[woff]    : 0.f;

            size_t idx = base + (size_t)hc*ROW4 + t;
            float4 bv = b_in[idx];

            float4 ax, dn;
            ax.x = sc.x + wxm*(sc.x-sl.x) - wxp*(sr.x-sc.x) + wym*(sc.x-su.x) - wyp*(sd.x-sc.x);
            ax.y = sc.y + wxm*(sc.y-sl.y) - wxp*(sr.y-sc.y) + wym*(sc.y-su.y) - wyp*(sd.y-sc.y);
            ax.z = sc.z + wxm*(sc.z-sl.z) - wxp*(sr.z-sc.z) + wym*(sc.z-su.z) - wyp*(sd.z-sc.z);
            ax.w = sc.w + wxm*(sc.w-sl.w) - wxp*(sr.w-sc.w) + wym*(sc.w-su.w) - wyp*(sd.w-sc.w);

            dn.x = c1*d_pipe.x + c2*(bv.x - ax.x);
            dn.y = c1*d_pipe.y + c2*(bv.y - ax.y);
            dn.z = c1*d_pipe.z + c2*(bv.z - ax.z);
            dn.w = c1*d_pipe.w + c2*(bv.w - ax.w);

            if (!INIT) x_out[idx] = sc;
            d_out[idx] = dn;
        }
        d_pipe = d_ld;
    }
}

// -------------------- final: x += d, transpose back to (B,D,H,W) ----------
__global__ void finish_kernel(const float* __restrict__ x,
                              const float* __restrict__ d,
                              float* __restrict__ out)
{
    __shared__ float sm[32*17];
    int blk = blockIdx.x;
    int wt = blk % (WW/32); blk /= (WW/32);
    int h  = blk % HH;      blk /= HH;
    int b  = blk;
    int w0 = wt * 32;
    int t = threadIdx.x;              // 512
    {
        size_t src = ((((size_t)b*HH + h)*WW) + w0)*DD + t;
        int wl = t >> 4, c = t & 15;
        sm[wl*17 + c] = x[src] + d[src];
    }
    __syncthreads();
    {
        int c = t >> 5, wl = t & 31;
        out[(((size_t)b*DD + c)*HH + h)*WW + w0 + wl] = sm[wl*17 + c];
    }
}

// -------------------- launch --------------------
extern "C" void kernel_launch(void* const* d_in, const int* in_sizes, int n_in,
                              void* d_out, int out_size)
{
    const float* ae  = (const float*)d_in[0];   // (B,D,H,W)
    const float* wxy = (const float*)d_in[1];   // (B,2,H,W)
    float* out = (float*)d_out;                 // (B,D,H,W)

    float4 *bt, *xb, *db;
    cudaGetSymbolAddress((void**)&bt, g_bt);
    cudaGetSymbolAddress((void**)&xb, g_x);
    cudaGetSymbolAddress((void**)&db, g_d);
    float4* xbuf[2] = { xb, xb + NV4 };
    float4* dbuf[2] = { db, db + NV4 };

    const int TGRID = BB*HH*(WW/32);   // 10240
    transpose_in_kernel<<<TGRID, 512>>>(ae, (float*)bt);

    const int IGRID = BB*NCHUNK;       // 256 blocks x 640 threads
    // d0 = (b - A b)/theta   (x0 = b, read directly from bt)
    cheb_iter<true><<<IGRID, ROW4>>>(bt, bt, bt, wxy,
                                     xbuf[0], dbuf[0],
                                     0.f, (float)(1.0/THETA));

    const double sigma1 = THETA / DELTA;   // 1.25
    double rho_prev = 1.0 / sigma1;
    const float4* x_cur = bt;
    const float4* d_cur = dbuf[0];
    for (int k = 1; k <= N_FULL; ++k) {
        double rho = 1.0 / (2.0*sigma1 - rho_prev);
        float c1 = (float)(rho * rho_prev);
        float c2 = (float)(2.0 * rho / DELTA);
        float4* x_o = xbuf[k & 1];
        float4* d_o = dbuf[k & 1];
        cheb_iter<false><<<IGRID, ROW4>>>(x_cur, d_cur, bt, wxy, x_o, d_o, c1, c2);
        x_cur = x_o; d_cur = d_o;
        rho_prev = rho;
    }

    // x_final = x + d, written back in (B,D,H,W)
    finish_kernel<<<TGRID, 512>>>((const float*)x_cur, (const float*)d_cur, out);
}

// round 2
// speedup vs baseline: 2.2629x; 2.2629x over previous
#include <cuda_runtime.h>

// Problem constants
#define BB 16
#define DD 16
#define HH 128
#define WW 160
#define ROW4   (WW*4)        // 640 float4 per (b,h) row in (B,H,W,D) layout
#define TH     8             // rows per block in iteration kernel
#define NCHUNK (HH/TH)       // 16
#define PLANE4 (HH*WW*4)     // float4 per image
#define NV4    (BB*HH*WW*4)  // total float4 per field

// Chebyshev on spectrum [1, 9]
#define THETA 5.0
#define DELTA 4.0
#define N_UPDATES 20
#define N_FULL (N_UPDATES-1)

__device__ float4 g_bt[NV4];      // b in (B,H,W,D) layout
__device__ float4 g_x[2][NV4];    // x ping-pong (in-place overwrite of x_{k-1})

// -------------------- transpose (B,D,H,W) -> (B,H,W,D) --------------------
__global__ void transpose_in_kernel(const float* __restrict__ ae,
                                    float* __restrict__ bt)
{
    __shared__ float sm[32*17];
    int blk = blockIdx.x;
    int wt = blk % (WW/32); blk /= (WW/32);
    int h  = blk % HH;      blk /= HH;
    int b  = blk;
    int w0 = wt * 32;
    int t = threadIdx.x;              // 512 threads
    {
        int c = t >> 5, wl = t & 31;
        float v = ae[(((size_t)b*DD + c)*HH + h)*WW + w0 + wl];
        sm[wl*17 + c] = v;
    }
    __syncthreads();
    {
        bt[((((size_t)b*HH + h)*WW) + w0)*DD + t] = sm[(t >> 4)*17 + (t & 15)];
    }
}

// -------------------- three-term Chebyshev iteration --------------------
// x_out = x + c1*(x - x_km1) + c2*(b - A x)
// x_km1 is read only at the output element, so x_out may alias x_km1
// (same-thread read-then-write). No __restrict__ on those two.
__global__ void __launch_bounds__(ROW4)
cheb3(const float4* __restrict__ x_in,
      const float4* x_km1,
      const float4* __restrict__ b_in,
      const float*  __restrict__ wxy,
      float4* x_out,
      float c1, float c2)
{
    __shared__ float4 sring[4][ROW4];   // 40KB ring of x rows
    const int t  = threadIdx.x;         // 640
    const int w  = t >> 2;
    const int blk = blockIdx.x;
    const int bi  = blk / NCHUNK;
    const int h0  = (blk - bi*NCHUNK) * TH;
    const size_t base = (size_t)bi * PLANE4;
    const float* wx = wxy + ((size_t)bi*2    )*HH*WW;
    const float* wy = wxy + ((size_t)bi*2 + 1)*HH*WW;

    #pragma unroll 1
    for (int hh = h0-1; hh <= h0+TH; ++hh) {
        float4 s = make_float4(0.f,0.f,0.f,0.f);
        if (hh >= 0 && hh < HH) {
            s = x_in[base + (size_t)hh*ROW4 + t];
        }
        sring[hh & 3][t] = s;
        __syncthreads();

        const int hc = hh - 1;
        if (hc >= h0 && hc < h0 + TH) {
            const float4 z  = make_float4(0.f,0.f,0.f,0.f);
            float4 sc = sring[hc & 3][t];
            float4 sl = (w > 0)     ? sring[hc & 3][t-4] : z;
            float4 sr = (w < WW-1)  ? sring[hc & 3][t+4] : z;
            float4 su = sring[(hc-1) & 3][t];   // zeros stored for hh = -1
            float4 sd = sring[(hc+1) & 3][t];   // zeros stored for hh = HH

            int woff  = hc*WW + w;
            float wxm = (w > 0)     ? wx[woff-1]  : 0.f;
            float wxp = (w < WW-1)  ? wx[woff]    : 0.f;
            float wym = (hc > 0)    ? wy[woff-WW] : 0.f;
            float wyp = (hc < HH-1) ? wy[woff]    : 0.f;

            size_t idx = base + (size_t)hc*ROW4 + t;
            float4 bv = b_in[idx];
            float4 xm = x_km1[idx];      // load BEFORE possibly-aliased store

            float4 ax, xn;
            ax.x = sc.x + wxm*(sc.x-sl.x) - wxp*(sr.x-sc.x) + wym*(sc.x-su.x) - wyp*(sd.x-sc.x);
            ax.y = sc.y + wxm*(sc.y-sl.y) - wxp*(sr.y-sc.y) + wym*(sc.y-su.y) - wyp*(sd.y-sc.y);
            ax.z = sc.z + wxm*(sc.z-sl.z) - wxp*(sr.z-sc.z) + wym*(sc.z-su.z) - wyp*(sd.z-sc.z);
            ax.w = sc.w + wxm*(sc.w-sl.w) - wxp*(sr.w-sc.w) + wym*(sc.w-su.w) - wyp*(sd.w-sc.w);

            xn.x = sc.x + c1*(sc.x - xm.x) + c2*(bv.x - ax.x);
            xn.y = sc.y + c1*(sc.y - xm.y) + c2*(bv.y - ax.y);
            xn.z = sc.z + c1*(sc.z - xm.z) + c2*(bv.z - ax.z);
            xn.w = sc.w + c1*(sc.w - xm.w) + c2*(bv.w - ax.w);

            x_out[idx] = xn;
        }
    }
}

// -------------------- final transpose back to (B,D,H,W) ----------
__global__ void finish_kernel(const float* __restrict__ x,
                              float* __restrict__ out)
{
    __shared__ float sm[32*17];
    int blk = blockIdx.x;
    int wt = blk % (WW/32); blk /= (WW/32);
    int h  = blk % HH;      blk /= HH;
    int b  = blk;
    int w0 = wt * 32;
    int t = threadIdx.x;              // 512
    {
        size_t src = ((((size_t)b*HH + h)*WW) + w0)*DD + t;
        sm[(t >> 4)*17 + (t & 15)] = x[src];
    }
    __syncthreads();
    {
        int c = t >> 5, wl = t & 31;
        out[(((size_t)b*DD + c)*HH + h)*WW + w0 + wl] = sm[wl*17 + c];
    }
}

// -------------------- launch --------------------
extern "C" void kernel_launch(void* const* d_in, const int* in_sizes, int n_in,
                              void* d_out, int out_size)
{
    const float* ae  = (const float*)d_in[0];   // (B,D,H,W)
    const float* wxy = (const float*)d_in[1];   // (B,2,H,W)
    float* out = (float*)d_out;                 // (B,D,H,W)

    float4 *bt, *xb;
    cudaGetSymbolAddress((void**)&bt, g_bt);
    cudaGetSymbolAddress((void**)&xb, g_x);
    float4* xbuf[2] = { xb, xb + NV4 };

    const int TGRID = BB*HH*(WW/32);   // 10240
    transpose_in_kernel<<<TGRID, 512>>>(ae, (float*)bt);

    const int IGRID = BB*NCHUNK;       // 256 blocks x 640 threads
    // Update 1: x_1 = b + (1/theta)(b - A b)   (x_0 = b, xm unused via c1=0)
    cheb3<<<IGRID, ROW4>>>(bt, bt, bt, wxy, xbuf[0], 0.f, (float)(1.0/THETA));

    const double sigma1 = THETA / DELTA;   // 1.25
    double rho_prev = 1.0 / sigma1;
    const float4* x_cur = xbuf[0];   // x_1
    const float4* x_prev = bt;       // x_0 = b
    for (int k = 1; k <= N_FULL; ++k) {
        double rho = 1.0 / (2.0*sigma1 - rho_prev);
        float c1 = (float)(rho * rho_prev);
        float c2 = (float)(2.0 * rho / DELTA);
        float4* x_o = xbuf[k & 1];   // k=1 writes xbuf[1] (x_prev is bt, kept intact);
                                     // k>=2 overwrites the buffer holding x_{k-1} in-place
        cheb3<<<IGRID, ROW4>>>(x_cur, x_prev, bt, wxy, x_o, c1, c2);
        x_prev = x_cur;
        x_cur  = x_o;
        rho_prev = rho;
    }

    finish_kernel<<<TGRID, 512>>>((const float*)x_cur, out);
}

// round 3
// speedup vs baseline: 4.1487x; 1.8333x over previous
#include <cuda_runtime.h>

// Problem constants
#define BB 16
#define DD 16
#define HH 128
#define WW 160
#define ROW4   (WW*4)        // 640 float4 per (b,h) row in (B,H,W,D) layout
#define TH     8             // output rows per block
#define NCHUNK (HH/TH)       // 16
#define PLANE4 (HH*WW*4)
#define NV4    (BB*HH*WW*4)

// Chebyshev on spectrum [1, 9]
#define THETA 5.0
#define DELTA 4.0
#define N_DOUBLE 6           // 6 fused launches = 12 single updates

__device__ float4 g_bt[NV4];      // b in (B,H,W,D) layout
__device__ float4 g_x[2][NV4];    // even-iterate ping-pong

// -------------------- transpose (B,D,H,W) -> (B,H,W,D) --------------------
__global__ void transpose_in_kernel(const float* __restrict__ ae,
                                    float* __restrict__ bt)
{
    __shared__ float sm[32*17];
    int blk = blockIdx.x;
    int wt = blk % (WW/32); blk /= (WW/32);
    int h  = blk % HH;      blk /= HH;
    int b  = blk;
    int w0 = wt * 32;
    int t = threadIdx.x;              // 512 threads
    {
        int c = t >> 5, wl = t & 31;
        sm[wl*17 + c] = ae[(((size_t)b*DD + c)*HH + h)*WW + w0 + wl];
    }
    __syncthreads();
    bt[((((size_t)b*HH + h)*WW) + w0)*DD + t] = sm[(t >> 4)*17 + (t & 15)];
}

// -------------------- fused double Chebyshev step --------------------
// r = b - A x            (A = I + weighted 5-pt Laplacian)
// x_out = g1*x + g2*x_km2 + g3*r + g4*(A r)
// x_km2 read only at output element -> x_out may alias x_km2.
extern __shared__ float4 s_mem[];   // [2][4][ROW4] : x ring, r ring (80KB)

__global__ void __launch_bounds__(ROW4)
cheb_dbl(const float4* __restrict__ x_in,
         const float4* x_km2,
         const float4* __restrict__ b_in,
         const float*  __restrict__ wxy,
         float4* x_out,
         float g1, float g2, float g3, float g4)
{
    float4 (*xring)[ROW4] = (float4 (*)[ROW4])s_mem;
    float4 (*rring)[ROW4] = (float4 (*)[ROW4])(s_mem + 4*ROW4);

    const int t  = threadIdx.x;         // 640
    const int w  = t >> 2;
    const int blk = blockIdx.x;
    const int bi  = blk / NCHUNK;
    const int h0  = (blk - bi*NCHUNK) * TH;
    const size_t base = (size_t)bi * PLANE4;
    const float* wx = wxy + ((size_t)bi*2    )*HH*WW;
    const float* wy = wxy + ((size_t)bi*2 + 1)*HH*WW;
    const float4 z = make_float4(0.f,0.f,0.f,0.f);

    #pragma unroll 1
    for (int hh = h0-2; hh <= h0+TH+1; ++hh) {
        // ---- stage 0: load x row hh into ring
        float4 xv = z;
        if (hh >= 0 && hh < HH)
            xv = x_in[base + (size_t)hh*ROW4 + t];
        xring[hh & 3][t] = xv;
        __syncthreads();

        // ---- stage 1: residual r at row h1 = hh-1 (pipeline range h0-1 .. h0+TH)
        const int h1 = hh - 1;
        if (h1 >= h0-1 && h1 <= h0+TH) {
            float4 rv = z;
            if (h1 >= 0 && h1 < HH) {
                float4 sc = xring[h1 & 3][t];
                float4 sl = (w > 0)     ? xring[h1 & 3][t-4] : z;
                float4 sr = (w < WW-1)  ? xring[h1 & 3][t+4] : z;
                float4 su = xring[(h1-1) & 3][t];
                float4 sd = xring[(h1+1) & 3][t];

                int woff  = h1*WW + w;
                float wxm = (w > 0)     ? wx[woff-1]  : 0.f;
                float wxp = (w < WW-1)  ? wx[woff]    : 0.f;
                float wym = (h1 > 0)    ? wy[woff-WW] : 0.f;
                float wyp = (h1 < HH-1) ? wy[woff]    : 0.f;

                float4 bv = b_in[base + (size_t)h1*ROW4 + t];
                rv.x = bv.x - (sc.x + wxm*(sc.x-sl.x) - wxp*(sr.x-sc.x) + wym*(sc.x-su.x) - wyp*(sd.x-sc.x));
                rv.y = bv.y - (sc.y + wxm*(sc.y-sl.y) - wxp*(sr.y-sc.y) + wym*(sc.y-su.y) - wyp*(sd.y-sc.y));
                rv.z = bv.z - (sc.z + wxm*(sc.z-sl.z) - wxp*(sr.z-sc.z) + wym*(sc.z-su.z) - wyp*(sd.z-sc.z));
                rv.w = bv.w - (sc.w + wxm*(sc.w-sl.w) - wxp*(sr.w-sc.w) + wym*(sc.w-su.w) - wyp*(sd.w-sc.w));
            }
            rring[h1 & 3][t] = rv;
        }
        __syncthreads();

        // ---- stage 2: output at row hc = hh-2
        const int hc = hh - 2;
        if (hc >= h0 && hc < h0 + TH) {
            float4 rc = rring[hc & 3][t];
            float4 rl = (w > 0)     ? rring[hc & 3][t-4] : z;
            float4 rr = (w < WW-1)  ? rring[hc & 3][t+4] : z;
            float4 ru = rring[(hc-1) & 3][t];
            float4 rd = rring[(hc+1) & 3][t];

            int woff  = hc*WW + w;
            float wxm = (w > 0)     ? wx[woff-1]  : 0.f;
            float wxp = (w < WW-1)  ? wx[woff]    : 0.f;
            float wym = (hc > 0)    ? wy[woff-WW] : 0.f;
            float wyp = (hc < HH-1) ? wy[woff]    : 0.f;

            size_t idx = base + (size_t)hc*ROW4 + t;
            float4 xc = xring[hc & 3][t];
            float4 xm = x_km2[idx];          // load BEFORE aliased store

            float4 ar, on;
            ar.x = rc.x + wxm*(rc.x-rl.x) - wxp*(rr.x-rc.x) + wym*(rc.x-ru.x) - wyp*(rd.x-rc.x);
            ar.y = rc.y + wxm*(rc.y-rl.y) - wxp*(rr.y-rc.y) + wym*(rc.y-ru.y) - wyp*(rd.y-rc.y);
            ar.z = rc.z + wxm*(rc.z-rl.z) - wxp*(rr.z-rc.z) + wym*(rc.z-ru.z) - wyp*(rd.z-rc.z);
            ar.w = rc.w + wxm*(rc.w-rl.w) - wxp*(rr.w-rc.w) + wym*(rc.w-ru.w) - wyp*(rd.w-rc.w);

            on.x = g1*xc.x + g2*xm.x + g3*rc.x + g4*ar.x;
            on.y = g1*xc.y + g2*xm.y + g3*rc.y + g4*ar.y;
            on.z = g1*xc.z + g2*xm.z + g3*rc.z + g4*ar.z;
            on.w = g1*xc.w + g2*xm.w + g3*rc.w + g4*ar.w;

            x_out[idx] = on;
        }
    }
}

// -------------------- final transpose back to (B,D,H,W) ----------
__global__ void finish_kernel(const float* __restrict__ x,
                              float* __restrict__ out)
{
    __shared__ float sm[32*17];
    int blk = blockIdx.x;
    int wt = blk % (WW/32); blk /= (WW/32);
    int h  = blk % HH;      blk /= HH;
    int b  = blk;
    int w0 = wt * 32;
    int t = threadIdx.x;              // 512
    {
        size_t src = ((((size_t)b*HH + h)*WW) + w0)*DD + t;
        sm[(t >> 4)*17 + (t & 15)] = x[src];
    }
    __syncthreads();
    {
        int c = t >> 5, wl = t & 31;
        out[(((size_t)b*DD + c)*HH + h)*WW + w0 + wl] = sm[wl*17 + c];
    }
}

// -------------------- launch --------------------
extern "C" void kernel_launch(void* const* d_in, const int* in_sizes, int n_in,
                              void* d_out, int out_size)
{
    const float* ae  = (const float*)d_in[0];   // (B,D,H,W)
    const float* wxy = (const float*)d_in[1];   // (B,2,H,W)
    float* out = (float*)d_out;                 // (B,D,H,W)

    float4 *bt, *xb;
    cudaGetSymbolAddress((void**)&bt, g_bt);
    cudaGetSymbolAddress((void**)&xb, g_x);
    float4* xbuf[2] = { xb, xb + NV4 };

    const int SMEM = 2 * 4 * ROW4 * (int)sizeof(float4);   // 81920
    cudaFuncSetAttribute(cheb_dbl, cudaFuncAttributeMaxDynamicSharedMemorySize, SMEM);

    const int TGRID = BB*HH*(WW/32);
    transpose_in_kernel<<<TGRID, 512>>>(ae, (float*)bt);

    // Chebyshev T_k(sigma), sigma = theta/delta = 1.25
    double tt[2*N_DOUBLE + 1];
    tt[0] = 1.0; tt[1] = THETA/DELTA;
    for (int k = 2; k <= 2*N_DOUBLE; ++k) tt[k] = 2.0*(THETA/DELTA)*tt[k-1] - tt[k-2];

    const double d2 = DELTA*DELTA;
    const int IGRID = BB*NCHUNK;       // 256 blocks x 640 threads

    // m=1: x_2 = x_0 + g3*r0 + g4*A r0, x_0 = b
    {
        float g3 = (float)(4.0*THETA/(d2*tt[2]));
        float g4 = (float)(-2.0/(d2*tt[2]));
        cheb_dbl<<<IGRID, ROW4, SMEM>>>(bt, bt, bt, wxy, xbuf[0],
                                        1.f, 0.f, g3, g4);
    }

    const float4* x_cur  = xbuf[0];   // x_2
    const float4* x_prev = bt;        // x_0 (= b, read-only)
    for (int m = 2; m <= N_DOUBLE; ++m) {
        double alpha = 2.0*tt[2*m-2]/tt[2*m];
        double beta  = tt[2*m-4]/tt[2*m];
        float g1 = (float)(1.0 + beta);
        float g2 = (float)(-beta);
        float g3 = (float)(4.0*alpha*THETA/d2);
        float g4 = (float)(-2.0*alpha/d2);
        // m=2 must not overwrite bt; m>=3 overwrites the x_{2m-4} buffer in place
        float4* x_o = (m == 2) ? xbuf[1] : (float4*)x_prev;
        cheb_dbl<<<IGRID, ROW4, SMEM>>>(x_cur, x_prev, bt, wxy, x_o, g1, g2, g3, g4);
        x_prev = x_cur;
        x_cur  = x_o;
    }

    finish_kernel<<<TGRID, 512>>>((const float*)x_cur, out);
}

// round 4
// speedup vs baseline: 4.4828x; 1.0805x over previous
#include <cuda_runtime.h>

// Problem constants
#define BB 16
#define DD 16
#define HH 128
#define WW 160
#define ROW4   (WW*4)        // 640 float4 per (b,h) row in (B,H,W,D) layout
#define TH     8             // output rows per block
#define NCHUNK (HH/TH)       // 16
#define PLANE4 (HH*WW*4)
#define NV4    (BB*HH*WW*4)

// Chebyshev on spectrum [1, 9]
#define THETA 5.0
#define DELTA 4.0
#define N_DOUBLE 6           // 6 fused launches = 12 single updates

#define MODE_INIT 0
#define MODE_MID  1
#define MODE_LAST 2

__device__ float4 g_bt[NV4];      // b in (B,H,W,D) layout
__device__ float4 g_x[2][NV4];    // even-iterate ping-pong

// -------------------- transpose (B,D,H,W) -> (B,H,W,D) --------------------
__global__ void transpose_in_kernel(const float* __restrict__ ae,
                                    float* __restrict__ bt)
{
    __shared__ float sm[32*17];
    int blk = blockIdx.x;
    int wt = blk % (WW/32); blk /= (WW/32);
    int h  = blk % HH;      blk /= HH;
    int b  = blk;
    int w0 = wt * 32;
    int t = threadIdx.x;              // 512 threads
    {
        int c = t >> 5, wl = t & 31;
        sm[wl*17 + c] = ae[(((size_t)b*DD + c)*HH + h)*WW + w0 + wl];
    }
    __syncthreads();
    bt[((((size_t)b*HH + h)*WW) + w0)*DD + t] = sm[(t >> 4)*17 + (t & 15)];
}

// -------------------- fused double Chebyshev step --------------------
// r = b - A x            (A = I + weighted 5-pt Laplacian)
// x_next = g1*x + g2*x_km2 + g3*r + g4*(A r)
// MODE_INIT: x_in == b_in (b reused from x ring), g2 = 0 (xm load skipped)
// MODE_MID : full form; x_km2 read only at output element -> may alias x_out
// MODE_LAST: result written directly to `out` in (B,D,H,W) layout
extern __shared__ float4 s_mem[];   // [2][4][ROW4] : x ring, r ring (80KB)

template<int MODE>
__global__ void __launch_bounds__(ROW4)
cheb_dbl(const float4* __restrict__ x_in,
         const float4* x_km2,
         const float4* __restrict__ b_in,
         const float*  __restrict__ wxy,
         float4* x_out,
         float*  out_t,
         float g1, float g2, float g3, float g4)
{
    float4 (*xring)[ROW4] = (float4 (*)[ROW4])s_mem;
    float4 (*rring)[ROW4] = (float4 (*)[ROW4])(s_mem + 4*ROW4);

    const int t  = threadIdx.x;         // 640
    const int w  = t >> 2;
    const int blk = blockIdx.x;
    const int bi  = blk / NCHUNK;
    const int h0  = (blk - bi*NCHUNK) * TH;
    const size_t base = (size_t)bi * PLANE4;
    const float* wx = wxy + ((size_t)bi*2    )*HH*WW;
    const float* wy = wxy + ((size_t)bi*2 + 1)*HH*WW;
    const float4 z = make_float4(0.f,0.f,0.f,0.f);

    #pragma unroll 1
    for (int hh = h0-2; hh <= h0+TH+1; ++hh) {
        // ---- stage 0: load x row hh into ring
        float4 xv = z;
        if (hh >= 0 && hh < HH)
            xv = x_in[base + (size_t)hh*ROW4 + t];
        xring[hh & 3][t] = xv;
        __syncthreads();

        // ---- stage 1: residual r at row h1 = hh-1
        const int h1 = hh - 1;
        if (h1 >= h0-1 && h1 <= h0+TH) {
            float4 rv = z;
            if (h1 >= 0 && h1 < HH) {
                float4 sc = xring[h1 & 3][t];
                float4 sl = (w > 0)     ? xring[h1 & 3][t-4] : z;
                float4 sr = (w < WW-1)  ? xring[h1 & 3][t+4] : z;
                float4 su = xring[(h1-1) & 3][t];
                float4 sd = xring[(h1+1) & 3][t];

                int woff  = h1*WW + w;
                float wxm = (w > 0)     ? wx[woff-1]  : 0.f;
                float wxp = (w < WW-1)  ? wx[woff]    : 0.f;
                float wym = (h1 > 0)    ? wy[woff-WW] : 0.f;
                float wyp = (h1 < HH-1) ? wy[woff]    : 0.f;

                float4 bv;
                if (MODE == MODE_INIT) bv = sc;   // b == x_in
                else bv = b_in[base + (size_t)h1*ROW4 + t];

                rv.x = bv.x - (sc.x + wxm*(sc.x-sl.x) - wxp*(sr.x-sc.x) + wym*(sc.x-su.x) - wyp*(sd.x-sc.x));
                rv.y = bv.y - (sc.y + wxm*(sc.y-sl.y) - wxp*(sr.y-sc.y) + wym*(sc.y-su.y) - wyp*(sd.y-sc.y));
                rv.z = bv.z - (sc.z + wxm*(sc.z-sl.z) - wxp*(sr.z-sc.z) + wym*(sc.z-su.z) - wyp*(sd.z-sc.z));
                rv.w = bv.w - (sc.w + wxm*(sc.w-sl.w) - wxp*(sr.w-sc.w) + wym*(sc.w-su.w) - wyp*(sd.w-sc.w));
            }
            rring[h1 & 3][t] = rv;
        }
        __syncthreads();

        // ---- stage 2: output at row hc = hh-2
        const int hc = hh - 2;
        if (hc >= h0 && hc < h0 + TH) {
            float4 rc = rring[hc & 3][t];
            float4 rl = (w > 0)     ? rring[hc & 3][t-4] : z;
            float4 rr = (w < WW-1)  ? rring[hc & 3][t+4] : z;
            float4 ru = rring[(hc-1) & 3][t];
            float4 rd = rring[(hc+1) & 3][t];

            int woff  = hc*WW + w;
            float wxm = (w > 0)     ? wx[woff-1]  : 0.f;
            float wxp = (w < WW-1)  ? wx[woff]    : 0.f;
            float wym = (hc > 0)    ? wy[woff-WW] : 0.f;
            float wyp = (hc < HH-1) ? wy[woff]    : 0.f;

            size_t idx = base + (size_t)hc*ROW4 + t;
            float4 xc = xring[hc & 3][t];

            float4 ar, on;
            ar.x = rc.x + wxm*(rc.x-rl.x) - wxp*(rr.x-rc.x) + wym*(rc.x-ru.x) - wyp*(rd.x-rc.x);
            ar.y = rc.y + wxm*(rc.y-rl.y) - wxp*(rr.y-rc.y) + wym*(rc.y-ru.y) - wyp*(rd.y-rc.y);
            ar.z = rc.z + wxm*(rc.z-rl.z) - wxp*(rr.z-rc.z) + wym*(rc.z-ru.z) - wyp*(rd.z-rc.z);
            ar.w = rc.w + wxm*(rc.w-rl.w) - wxp*(rr.w-rc.w) + wym*(rc.w-ru.w) - wyp*(rd.w-rc.w);

            if (MODE == MODE_INIT) {
                on.x = g1*xc.x + g3*rc.x + g4*ar.x;
                on.y = g1*xc.y + g3*rc.y + g4*ar.y;
                on.z = g1*xc.z + g3*rc.z + g4*ar.z;
                on.w = g1*xc.w + g3*rc.w + g4*ar.w;
            } else {
                float4 xm = x_km2[idx];      // load BEFORE aliased store
                on.x = g1*xc.x + g2*xm.x + g3*rc.x + g4*ar.x;
                on.y = g1*xc.y + g2*xm.y + g3*rc.y + g4*ar.y;
                on.z = g1*xc.z + g2*xm.z + g3*rc.z + g4*ar.z;
                on.w = g1*xc.w + g2*xm.w + g3*rc.w + g4*ar.w;
            }

            if (MODE == MODE_LAST) {
                // direct store in (B,D,H,W): 4 channels, stride H*W apart;
                // 8 consecutive-w lanes per channel -> full 32B sectors.
                int d0 = (t & 3) * 4;
                float* o = out_t + (((size_t)(bi*DD + d0))*HH + hc)*WW + w;
                o[0]            = on.x;
                o[HH*WW]        = on.y;
                o[2*(HH*WW)]    = on.z;
                o[3*(size_t)(HH*WW)] = on.w;
            } else {
                x_out[idx] = on;
            }
        }
    }
}

// -------------------- launch --------------------
extern "C" void kernel_launch(void* const* d_in, const int* in_sizes, int n_in,
                              void* d_out, int out_size)
{
    const float* ae  = (const float*)d_in[0];   // (B,D,H,W)
    const float* wxy = (const float*)d_in[1];   // (B,2,H,W)
    float* out = (float*)d_out;                 // (B,D,H,W)

    float4 *bt, *xb;
    cudaGetSymbolAddress((void**)&bt, g_bt);
    cudaGetSymbolAddress((void**)&xb, g_x);
    float4* xbuf[2] = { xb, xb + NV4 };

    const int SMEM = 2 * 4 * ROW4 * (int)sizeof(float4);   // 81920
    cudaFuncSetAttribute(cheb_dbl<MODE_INIT>, cudaFuncAttributeMaxDynamicSharedMemorySize, SMEM);
    cudaFuncSetAttribute(cheb_dbl<MODE_MID>,  cudaFuncAttributeMaxDynamicSharedMemorySize, SMEM);
    cudaFuncSetAttribute(cheb_dbl<MODE_LAST>, cudaFuncAttributeMaxDynamicSharedMemorySize, SMEM);

    const int TGRID = BB*HH*(WW/32);
    transpose_in_kernel<<<TGRID, 512>>>(ae, (float*)bt);

    // Chebyshev T_k(sigma), sigma = theta/delta = 1.25
    double tt[2*N_DOUBLE + 1];
    tt[0] = 1.0; tt[1] = THETA/DELTA;
    for (int k = 2; k <= 2*N_DOUBLE; ++k) tt[k] = 2.0*(THETA/DELTA)*tt[k-1] - tt[k-2];

    const double d2 = DELTA*DELTA;
    const int IGRID = BB*NCHUNK;       // 256 blocks x 640 threads

    // m=1: x_2 = x_0 + g3*r0 + g4*A r0, x_0 = b
    {
        float g3 = (float)(4.0*THETA/(d2*tt[2]));
        float g4 = (float)(-2.0/(d2*tt[2]));
        cheb_dbl<MODE_INIT><<<IGRID, ROW4, SMEM>>>(bt, bt, bt, wxy, xbuf[0], out,
                                                   1.f, 0.f, g3, g4);
    }

    const float4* x_cur  = xbuf[0];   // x_2
    const float4* x_prev = bt;        // x_0 (= b, read-only)
    for (int m = 2; m <= N_DOUBLE; ++m) {
        double alpha = 2.0*tt[2*m-2]/tt[2*m];
        double beta  = tt[2*m-4]/tt[2*m];
        float g1 = (float)(1.0 + beta);
        float g2 = (float)(-beta);
        float g3 = (float)(4.0*alpha*THETA/d2);
        float g4 = (float)(-2.0*alpha/d2);
        if (m < N_DOUBLE) {
            // m=2 must not overwrite bt; m>=3 overwrites x_{2m-4} in place
            float4* x_o = (m == 2) ? xbuf[1] : (float4*)x_prev;
            cheb_dbl<MODE_MID><<<IGRID, ROW4, SMEM>>>(x_cur, x_prev, bt, wxy, x_o, out,
                                                      g1, g2, g3, g4);
            x_prev = x_cur;
            x_cur  = x_o;
        } else {
            // final double-step writes straight to d_out in (B,D,H,W)
            cheb_dbl<MODE_LAST><<<IGRID, ROW4, SMEM>>>(x_cur, x_prev, bt, wxy, nullptr, out,
                                                       g1, g2, g3, g4);
        }
    }
}

// round 5
// speedup vs baseline: 5.2004x; 1.1601x over previous
#include <cuda_runtime.h>

// Problem constants
#define BB 16
#define DD 16
#define HH 128
#define WW 160
#define ROW4   (WW*4)        // 640 float4 per (b,h) row in (B,H,W,D) layout
#define TH     8             // output rows per block
#define NCHUNK (HH/TH)       // 16
#define PLANE4 (HH*WW*4)
#define NV4    (BB*HH*WW*4)
#define HW     (HH*WW)

// Chebyshev on spectrum [1, 9]
#define THETA 5.0
#define DELTA 4.0
#define N_DOUBLE 6           // 6 fused double-steps = 12 single updates

#define MODE_INIT 0
#define MODE_MID  1
#define MODE_LAST 2

__device__ float4 g_bt[NV4];      // b in (B,H,W,D) layout
__device__ float4 g_x[2][NV4];    // even-iterate ping-pong

// -------------------- fused double Chebyshev step --------------------
// r = b - A x            (A = I + weighted 5-pt Laplacian)
// x_next = g1*x + g2*x_km2 + g3*r + g4*(A r)
// Single __syncthreads per row-iteration: output retired at hc = hh-3 so
// stage1/stage2 only consume ring rows written in earlier barrier regions
// (or pre-sync this region). Ring depth 4, slot distance of any concurrent
// write vs live read is 3 mod 4 -> race-free.
// MODE_INIT: x == b; reads ae directly in (B,D,H,W) and emits bt (transposed b).
// MODE_LAST: writes result directly to out in (B,D,H,W).
extern __shared__ float4 s_mem[];   // [2][4][ROW4] (80KB)

template<int MODE>
__global__ void __launch_bounds__(ROW4, 2)
cheb_dbl(const float4* __restrict__ x_in,
         const float4* x_km2,
         const float4* __restrict__ b_in,
         const float*  __restrict__ ae,
         const float*  __restrict__ wxy,
         float4* x_out,
         float4* bt_w,
         float*  out_t,
         float g1, float g2, float g3, float g4)
{
    float4 (*xring)[ROW4] = (float4 (*)[ROW4])s_mem;
    float4 (*rring)[ROW4] = (float4 (*)[ROW4])(s_mem + 4*ROW4);

    const int t  = threadIdx.x;         // 640
    const int w  = t >> 2;
    const int q  = t & 3;               // channel quarter: channels q*4..q*4+3
    const int blk = blockIdx.x;
    const int bi  = blk / NCHUNK;
    const int h0  = (blk - bi*NCHUNK) * TH;
    const size_t base = (size_t)bi * PLANE4;
    const float* wx = wxy + ((size_t)bi*2    )*HW;
    const float* wy = wxy + ((size_t)bi*2 + 1)*HW;
    const float4 z = make_float4(0.f,0.f,0.f,0.f);

    auto loadx = [&](int hh) -> float4 {
        float4 v = z;
        if (hh >= 0 && hh < HH && hh <= h0+TH+1) {
            if (MODE == MODE_INIT) {
                const float* src = ae + (((size_t)(bi*DD + q*4))*HH + hh)*WW + w;
                v.x = src[0];
                v.y = src[HW];
                v.z = src[2*HW];
                v.w = src[3*(size_t)HW];
            } else {
                v = x_in[base + (size_t)hh*ROW4 + t];
            }
        }
        return v;
    };

    float4 xv = loadx(h0-2);

    #pragma unroll 1
    for (int hh = h0-2; hh <= h0+TH+2; ++hh) {
        // ---- stage 0: publish x row hh, prefetch next
        if (hh <= h0+TH+1) {
            xring[hh & 3][t] = xv;
            if (MODE == MODE_INIT && hh >= 0 && hh < HH)
                bt_w[base + (size_t)hh*ROW4 + t] = xv;   // transposed b side-product
        }
        float4 xnext = loadx(hh+1);
        __syncthreads();

        // ---- stage 1: residual r at h1 = hh-1
        const int h1 = hh - 1;
        if (h1 >= h0-1 && h1 <= h0+TH) {
            float4 rv = z;
            if (h1 >= 0 && h1 < HH) {
                float4 sc = xring[h1 & 3][t];
                float4 sl = (w > 0)     ? xring[h1 & 3][t-4] : z;
                float4 sr = (w < WW-1)  ? xring[h1 & 3][t+4] : z;
                float4 su = xring[(h1-1) & 3][t];
                float4 sd = xring[(h1+1) & 3][t];

                int woff  = h1*WW + w;
                float wxm = (w > 0)     ? wx[woff-1]  : 0.f;
                float wxp = (w < WW-1)  ? wx[woff]    : 0.f;
                float wym = (h1 > 0)    ? wy[woff-WW] : 0.f;
                float wyp = (h1 < HH-1) ? wy[woff]    : 0.f;

                float4 bv;
                if (MODE == MODE_INIT) bv = sc;   // b == x
                else bv = b_in[base + (size_t)h1*ROW4 + t];

                rv.x = bv.x - (sc.x + wxm*(sc.x-sl.x) - wxp*(sr.x-sc.x) + wym*(sc.x-su.x) - wyp*(sd.x-sc.x));
                rv.y = bv.y - (sc.y + wxm*(sc.y-sl.y) - wxp*(sr.y-sc.y) + wym*(sc.y-su.y) - wyp*(sd.y-sc.y));
                rv.z = bv.z - (sc.z + wxm*(sc.z-sl.z) - wxp*(sr.z-sc.z) + wym*(sc.z-su.z) - wyp*(sd.z-sc.z));
                rv.w = bv.w - (sc.w + wxm*(sc.w-sl.w) - wxp*(sr.w-sc.w) + wym*(sc.w-su.w) - wyp*(sd.w-sc.w));
            }
            rring[h1 & 3][t] = rv;
        }

        // ---- stage 2: output at hc = hh-3 (same barrier region; reads only
        //      ring rows written in earlier regions -> no extra sync needed)
        const int hc = hh - 3;
        if (hc >= h0 && hc < h0 + TH) {
            float4 rc = rring[hc & 3][t];
            float4 rl = (w > 0)     ? rring[hc & 3][t-4] : z;
            float4 rr = (w < WW-1)  ? rring[hc & 3][t+4] : z;
            float4 ru = rring[(hc-1) & 3][t];
            float4 rd = rring[(hc+1) & 3][t];

            int woff  = hc*WW + w;
            float wxm = (w > 0)     ? wx[woff-1]  : 0.f;
            float wxp = (w < WW-1)  ? wx[woff]    : 0.f;
            float wym = (hc > 0)    ? wy[woff-WW] : 0.f;
            float wyp = (hc < HH-1) ? wy[woff]    : 0.f;

            size_t idx = base + (size_t)hc*ROW4 + t;
            float4 xc = xring[hc & 3][t];

            float4 ar, on;
            ar.x = rc.x + wxm*(rc.x-rl.x) - wxp*(rr.x-rc.x) + wym*(rc.x-ru.x) - wyp*(rd.x-rc.x);
            ar.y = rc.y + wxm*(rc.y-rl.y) - wxp*(rr.y-rc.y) + wym*(rc.y-ru.y) - wyp*(rd.y-rc.y);
            ar.z = rc.z + wxm*(rc.z-rl.z) - wxp*(rr.z-rc.z) + wym*(rc.z-ru.z) - wyp*(rd.z-rc.z);
            ar.w = rc.w + wxm*(rc.w-rl.w) - wxp*(rr.w-rc.w) + wym*(rc.w-ru.w) - wyp*(rd.w-rc.w);

            if (MODE == MODE_INIT) {
                on.x = g1*xc.x + g3*rc.x + g4*ar.x;
                on.y = g1*xc.y + g3*rc.y + g4*ar.y;
                on.z = g1*xc.z + g3*rc.z + g4*ar.z;
                on.w = g1*xc.w + g3*rc.w + g4*ar.w;
            } else {
                float4 xm = x_km2[idx];      // load BEFORE aliased store
                on.x = g1*xc.x + g2*xm.x + g3*rc.x + g4*ar.x;
                on.y = g1*xc.y + g2*xm.y + g3*rc.y + g4*ar.y;
                on.z = g1*xc.z + g2*xm.z + g3*rc.z + g4*ar.z;
                on.w = g1*xc.w + g2*xm.w + g3*rc.w + g4*ar.w;
            }

            if (MODE == MODE_LAST) {
                // direct (B,D,H,W) store: 8-lane runs of consecutive w per
                // channel -> full 32B sectors, same sector count as float4.
                float* o = out_t + (((size_t)(bi*DD + q*4))*HH + hc)*WW + w;
                o[0]              = on.x;
                o[HW]             = on.y;
                o[2*HW]           = on.z;
                o[3*(size_t)HW]   = on.w;
            } else {
                x_out[idx] = on;
            }
        }
        xv = xnext;
    }
}

// -------------------- launch --------------------
extern "C" void kernel_launch(void* const* d_in, const int* in_sizes, int n_in,
                              void* d_out, int out_size)
{
    const float* ae  = (const float*)d_in[0];   // (B,D,H,W)
    const float* wxy = (const float*)d_in[1];   // (B,2,H,W)
    float* out = (float*)d_out;                 // (B,D,H,W)

    float4 *bt, *xb;
    cudaGetSymbolAddress((void**)&bt, g_bt);
    cudaGetSymbolAddress((void**)&xb, g_x);
    float4* xbuf[2] = { xb, xb + NV4 };

    const int SMEM = 2 * 4 * ROW4 * (int)sizeof(float4);   // 81920
    cudaFuncSetAttribute(cheb_dbl<MODE_INIT>, cudaFuncAttributeMaxDynamicSharedMemorySize, SMEM);
    cudaFuncSetAttribute(cheb_dbl<MODE_MID>,  cudaFuncAttributeMaxDynamicSharedMemorySize, SMEM);
    cudaFuncSetAttribute(cheb_dbl<MODE_LAST>, cudaFuncAttributeMaxDynamicSharedMemorySize, SMEM);

    // Chebyshev T_k(sigma), sigma = theta/delta = 1.25
    double tt[2*N_DOUBLE + 1];
    tt[0] = 1.0; tt[1] = THETA/DELTA;
    for (int k = 2; k <= 2*N_DOUBLE; ++k) tt[k] = 2.0*(THETA/DELTA)*tt[k-1] - tt[k-2];

    const double d2 = DELTA*DELTA;
    const int IGRID = BB*NCHUNK;       // 256 blocks x 640 threads

    // m=1: x_2 = x_0 + g3*r0 + g4*A r0, x_0 = b  (reads ae, emits bt)
    {
        float g3 = (float)(4.0*THETA/(d2*tt[2]));
        float g4 = (float)(-2.0/(d2*tt[2]));
        cheb_dbl<MODE_INIT><<<IGRID, ROW4, SMEM>>>(nullptr, nullptr, nullptr,
                                                   ae, wxy, xbuf[0], bt, nullptr,
                                                   1.f, 0.f, g3, g4);
    }

    const float4* x_cur  = xbuf[0];   // x_2
    const float4* x_prev = bt;        // x_0 (= b, read-only)
    for (int m = 2; m <= N_DOUBLE; ++m) {
        double alpha = 2.0*tt[2*m-2]/tt[2*m];
        double beta  = tt[2*m-4]/tt[2*m];
        float g1 = (float)(1.0 + beta);
        float g2 = (float)(-beta);
        float g3 = (float)(4.0*alpha*THETA/d2);
        float g4 = (float)(-2.0*alpha/d2);
        if (m < N_DOUBLE) {
            // m=2 must not overwrite bt; m>=3 overwrites x_{2m-4} in place
            float4* x_o = (m == 2) ? xbuf[1] : (float4*)x_prev;
            cheb_dbl<MODE_MID><<<IGRID, ROW4, SMEM>>>(x_cur, x_prev, bt,
                                                      nullptr, wxy, x_o, nullptr, nullptr,
                                                      g1, g2, g3, g4);
            x_prev = x_cur;
            x_cur  = x_o;
        } else {
            cheb_dbl<MODE_LAST><<<IGRID, ROW4, SMEM>>>(x_cur, x_prev, bt,
                                                       nullptr, wxy, nullptr, nullptr, out,
                                                       g1, g2, g3, g4);
        }
    }
}